// round 11
// baseline (speedup 1.0000x reference)
#include <cuda_runtime.h>

// AdaptiveFeaturePooling: 4-level ROIAlign (out=14, sr=2) + max over levels.
// SINGLE fused kernel, grid = R + 2048:
//  builders (bid < R): bilinear tables + mask + release-published worklist;
//    signal g_bdone; skip-fill own ROI slice (zero all invalid cells).
//  consumers (bid >= R): dynamically pop worklist entries (global ticket),
//    acquire-poll each entry until published, gather/compute (lanes =
//    channel_quarter x x_tap, 8 L1 lines per warp-gather, shfl butterfly),
//    store valid cells, zero the consumed entry for the next graph replay.
// Builders never wait; all builders fit in wave 1 -> consumer spins are safe.
// Last ticket block resets all counters (graph-replay deterministic).

#define OUTSZ  14
#define CELLS  196
#define CH     256
#define GSAMP  28           // OUTSZ*2
#define MAXROI 512
#define CGRID  2048
#define NF4    ((CH * CELLS) / 4)   // 12544 float4 per ROI slice
#define NGRP   (NF4 / CH)           // 49 float4 groups per channel

// tab[r][l][a][j] = {w0, w1, lo(bits), hi(bits)}
__device__ float4 g_tab[MAXROI][4][2][GSAMP];
__device__ unsigned g_work[MAXROI * CELLS];   // (r<<12)|(cell<<4)|m, 0 = unpublished
__device__ int g_count;                        // published entries (alloc order)
__device__ int g_bdone;                        // builders completed
__device__ int g_pop;                          // consumer ticket
__device__ int g_ticket;                       // exit ticket

__device__ __forceinline__ int ldacq_s32(const int* p)
{
    int v; asm volatile("ld.acquire.gpu.s32 %0, [%1];" : "=r"(v) : "l"(p)); return v;
}
__device__ __forceinline__ unsigned ldacq_u32(const unsigned* p)
{
    unsigned v; asm volatile("ld.acquire.gpu.u32 %0, [%1];" : "=r"(v) : "l"(p)); return v;
}
__device__ __forceinline__ void strel_u32(unsigned* p, unsigned v)
{
    asm volatile("st.release.gpu.u32 [%0], %1;" :: "l"(p), "r"(v) : "memory");
}

__global__ __launch_bounds__(256)
void afp_fused(const float* __restrict__ f0, const float* __restrict__ f1,
               const float* __restrict__ f2, const float* __restrict__ f3,
               const float* __restrict__ rois, int R, float* __restrict__ out)
{
    const int tid = threadIdx.x;
    const int bid = blockIdx.x;

    if (bid < R) {
        // ============================ BUILDER ============================
        __shared__ float s_w0[4][2][GSAMP];
        __shared__ float s_w1[4][2][GSAMP];
        __shared__ unsigned char s_m[CELLS];
        __shared__ unsigned char s_anyv[NGRP];

        const int r = bid;

        // Phase A: bilinear prep (reference fp32 op order, exactly).
        if (tid < 4 * 2 * GSAMP) {
            int l   = tid / (2 * GSAMP);
            int rem = tid - l * (2 * GSAMP);
            int a   = rem / GSAMP;       // 0=y, 1=x
            int j   = rem - a * GSAMP;

            float p1 = rois[r * 4 + (a == 0 ? 1 : 0)];
            float p2 = rois[r * 4 + (a == 0 ? 3 : 2)];
            #pragma unroll
            for (int i = 3; i >= 0; --i) {
                if (i >= l) {
                    float s = (float)(28 << i);
                    p1 = __fmul_rn(p1, s);
                    p2 = __fmul_rn(p2, s);
                }
            }
            float len  = fmaxf(__fadd_rn(p2, -p1), 1.0f);
            float t    = __fdiv_rn(len, 14.0f);
            float step = ((float)j + 0.5f) * 0.5f;
            float c    = __fadd_rn(p1, __fmul_rn(step, t));

            int L = 224 >> l;
            bool valid = (c >= -1.0f) && (c <= (float)L);
            c = fminf(fmaxf(c, 0.0f), (float)(L - 1));
            float lo   = floorf(c);
            float frac = __fadd_rn(c, -lo);
            int loi = (int)lo;
            int hii = loi + 1;
            if (loi >= L - 1) { loi = L - 1; hii = L - 1; frac = 0.0f; }
            float v  = valid ? 1.0f : 0.0f;
            float w0 = (1.0f - frac) * v;
            float w1 = frac * v;
            s_w0[l][a][j] = w0;
            s_w1[l][a][j] = w1;
            g_tab[r][l][a][j] = make_float4(w0, w1, __int_as_float(loi), __int_as_float(hii));
        }
        __syncthreads();    // g_tab[r] writes visible block-wide before publish

        // Phase B: mask + publish worklist entries (release store; consumers
        // may start on them immediately).
        if (tid < CELLS) {
            int py = tid / OUTSZ;
            int px = tid - py * OUTSZ;
            unsigned m = 0;
            #pragma unroll
            for (int l = 0; l < 4; ++l) {
                float wy = s_w0[l][0][2*py]   + s_w1[l][0][2*py]
                         + s_w0[l][0][2*py+1] + s_w1[l][0][2*py+1];
                float wx = s_w0[l][1][2*px]   + s_w1[l][1][2*px]
                         + s_w0[l][1][2*px+1] + s_w1[l][1][2*px+1];
                if (wy > 0.0f && wx > 0.0f) m |= (1u << l);
            }
            s_m[tid] = (unsigned char)m;
            if (m) {
                int pos = atomicAdd(&g_count, 1);
                strel_u32(&g_work[pos],
                          ((unsigned)r << 12) | ((unsigned)tid << 4) | m);
            }
        }
        __syncthreads();

        // All of this ROI's entries are published; count toward drain signal.
        if (tid == 0) {
            __threadfence();
            atomicAdd(&g_bdone, 1);
        }

        // Per-4-cell-group "any valid" flags for the fast fill path.
        if (tid < NGRP) {
            int k = tid * 4;
            s_anyv[tid] = (unsigned char)(s_m[k] | s_m[k+1] | s_m[k+2] | s_m[k+3]);
        }
        __syncthreads();

        // Skip-fill: zero all invalid cells of this ROI's slice.
        float* obase = out + (size_t)r * (CH * CELLS);
        float4* o4 = reinterpret_cast<float4*>(obase);
        const float4 z4 = make_float4(0.f, 0.f, 0.f, 0.f);
        int k = tid % NGRP;
        #pragma unroll 4
        for (int i = tid; i < NF4; i += 256) {
            if (!s_anyv[k]) {
                o4[i] = z4;
            } else {
                int cell0 = k * 4;
                float* p = obase + i * 4;
                #pragma unroll
                for (int q = 0; q < 4; ++q)
                    if (!s_m[cell0 + q]) p[q] = 0.0f;
            }
            k += 256 % NGRP;             // 11
            if (k >= NGRP) k -= NGRP;
        }
    } else {
        // ============================ CONSUMER ===========================
        __shared__ int se;
        const int xi = tid & 3;          // x-tap lane within 4-lane group
        const int cq = tid >> 2;         // channel quarter index 0..63
        const float* fl[4] = { f0, f1, f2, f3 };

        for (;;) {
            __syncthreads();
            if (tid == 0) se = atomicAdd(&g_pop, 1);
            __syncthreads();
            const int e = se;
            if (e >= MAXROI * CELLS) break;

            // Acquire-poll the entry until published; drain check via g_bdone.
            unsigned w = ldacq_u32(&g_work[e]);
            while (w == 0u) {
                if (ldacq_s32(&g_bdone) == R) {
                    w = ldacq_u32(&g_work[e]);   // final re-check
                    break;
                }
                __nanosleep(32);
                w = ldacq_u32(&g_work[e]);
            }
            if (w == 0u) break;          // e >= n: worklist drained

            int r    = (int)(w >> 12);
            int cell = (int)((w >> 4) & 0xFF);
            unsigned m = w & 0xF;
            int py = cell / OUTSZ;
            int px = cell - py * OUTSZ;
            int sy = 2 * py, sx = 2 * px;

            const size_t obase = (size_t)r * (CH * CELLS) + cell;

            #pragma unroll
            for (int p = 0; p < 4; ++p) {
                const int c = cq + 64 * p;
                float best = 0.0f;

                #pragma unroll
                for (int l = 0; l < 4; ++l) {
                    if (m & (1u << l)) {
                        const int W = 224 >> l;
                        const float* fc = fl[l] + (size_t)c * (W * W);

                        float4 ty0 = g_tab[r][l][0][sy];
                        float4 ty1 = g_tab[r][l][0][sy + 1];
                        float4 tx0 = g_tab[r][l][1][sx];
                        float4 tx1 = g_tab[r][l][1][sx + 1];

                        float wx; int x;
                        if (xi == 0)      { wx = tx0.x; x = __float_as_int(tx0.z); }
                        else if (xi == 1) { wx = tx0.y; x = __float_as_int(tx0.w); }
                        else if (xi == 2) { wx = tx1.x; x = __float_as_int(tx1.z); }
                        else              { wx = tx1.y; x = __float_as_int(tx1.w); }

                        int y0 = __float_as_int(ty0.z) * W;
                        int y1 = __float_as_int(ty0.w) * W;
                        int y2 = __float_as_int(ty1.z) * W;
                        int y3 = __float_as_int(ty1.w) * W;

                        float v0 = fc[y0 + x];
                        float v1 = fc[y1 + x];
                        float v2 = fc[y2 + x];
                        float v3 = fc[y3 + x];

                        float acc = wx * (ty0.x * v0 + ty0.y * v1
                                        + ty1.x * v2 + ty1.y * v3);
                        acc += __shfl_xor_sync(0xFFFFFFFFu, acc, 1);
                        acc += __shfl_xor_sync(0xFFFFFFFFu, acc, 2);

                        best = fmaxf(best, acc * 0.25f);
                    }
                }
                if (xi == 0)
                    out[obase + (size_t)c * CELLS] = best;
            }

            // Re-zero the consumed entry for the next graph replay.
            if (tid == 0) g_work[e] = 0u;
        }
    }

    // Self-reset: the LAST block to finish (all others already completed their
    // loops) zeroes the counters for the next replay.
    __syncthreads();
    if (tid == 0) {
        int t = atomicAdd(&g_ticket, 1);
        if (t == R + CGRID - 1) {
            g_count  = 0;
            g_bdone  = 0;
            g_pop    = 0;
            g_ticket = 0;
        }
    }
}

extern "C" void kernel_launch(void* const* d_in, const int* in_sizes, int n_in,
                              void* d_out, int out_size)
{
    const float* f0   = (const float*)d_in[0];
    const float* f1   = (const float*)d_in[1];
    const float* f2   = (const float*)d_in[2];
    const float* f3   = (const float*)d_in[3];
    const float* rois = (const float*)d_in[4];
    int R = in_sizes[4] / 4;

    afp_fused<<<R + CGRID, 256>>>(f0, f1, f2, f3, rois, R, (float*)d_out);
}

// round 12
// speedup vs baseline: 1.1126x; 1.1126x over previous
#include <cuda_runtime.h>

// AdaptiveFeaturePooling: 4-level ROIAlign (out=14, sr=2) + max over levels.
// SINGLE fused kernel, grid = R + 512:
//  builders (bid < R): bilinear tables + mask + release-published worklist;
//    signal g_bdone; skip-fill own ROI slice (zero invalid cells); then JOIN
//    the consumer pop loop (drains any remaining entries).
//  consumers (bid >= R): dynamically pop worklist entries; per entry, all 4
//    channel-phases' gathers are issued in one batch (16 independent LDGs per
//    thread -> one latency round), then shfl-butterfly reduce and store.
// Builders never wait and come first in the grid -> no scheduling deadlock.
// Counters self-reset via exit ticket (graph-replay deterministic).

#define OUTSZ  14
#define CELLS  196
#define CH     256
#define GSAMP  28           // OUTSZ*2
#define MAXROI 512
#define CGRID  512
#define NF4    ((CH * CELLS) / 4)   // 12544 float4 per ROI slice
#define NGRP   (NF4 / CH)           // 49 float4 groups per channel

// tab[r][l][a][j] = {w0, w1, lo(bits), hi(bits)}
__device__ float4 g_tab[MAXROI][4][2][GSAMP];
__device__ unsigned g_work[MAXROI * CELLS];   // (r<<12)|(cell<<4)|m, 0 = unpublished
__device__ int g_count;                        // published entries
__device__ int g_bdone;                        // builders done publishing
__device__ int g_pop;                          // consumer ticket
__device__ int g_ticket;                       // exit ticket

__device__ __forceinline__ int ldacq_s32(const int* p)
{
    int v; asm volatile("ld.acquire.gpu.s32 %0, [%1];" : "=r"(v) : "l"(p)); return v;
}
__device__ __forceinline__ unsigned ldacq_u32(const unsigned* p)
{
    unsigned v; asm volatile("ld.acquire.gpu.u32 %0, [%1];" : "=r"(v) : "l"(p)); return v;
}
__device__ __forceinline__ void strel_u32(unsigned* p, unsigned v)
{
    asm volatile("st.release.gpu.u32 [%0], %1;" :: "l"(p), "r"(v) : "memory");
}

struct ConsumeSmem { int e; unsigned w; };

// Pop-and-compute loop. All 256 threads of the block participate.
__device__ __forceinline__ void consume(
    const float* __restrict__ f0, const float* __restrict__ f1,
    const float* __restrict__ f2, const float* __restrict__ f3,
    float* __restrict__ out, int R, ConsumeSmem* cs)
{
    const int tid = threadIdx.x;
    const int xi  = tid & 3;             // x-tap lane within 4-lane group
    const int cq  = tid >> 2;            // channel quarter 0..63
    const float* fl[4] = { f0, f1, f2, f3 };

    for (;;) {
        __syncthreads();
        if (tid == 0) {
            int e = atomicAdd(&g_pop, 1);
            unsigned w = 0;
            if (e < MAXROI * CELLS) {
                w = ldacq_u32(&g_work[e]);
                while (w == 0u) {
                    if (ldacq_s32(&g_bdone) == R) { w = ldacq_u32(&g_work[e]); break; }
                    __nanosleep(32);
                    w = ldacq_u32(&g_work[e]);
                }
                if (w) g_work[e] = 0u;    // re-zero for next graph replay
            }
            cs->w = w;
        }
        __syncthreads();
        const unsigned w = cs->w;
        if (w == 0u) break;               // drained

        int r    = (int)(w >> 12);
        int cell = (int)((w >> 4) & 0xFF);
        unsigned m = w & 0xF;
        int py = cell / OUTSZ;
        int px = cell - py * OUTSZ;
        int sy = 2 * py, sx = 2 * px;

        const size_t obase = (size_t)r * (CH * CELLS) + cell;

        float best0 = 0.f, best1 = 0.f, best2 = 0.f, best3 = 0.f;

        #pragma unroll
        for (int l = 0; l < 4; ++l) {
            if (m & (1u << l)) {
                const int W = 224 >> l;
                float4 ty0 = g_tab[r][l][0][sy];
                float4 ty1 = g_tab[r][l][0][sy + 1];
                float4 tx0 = g_tab[r][l][1][sx];
                float4 tx1 = g_tab[r][l][1][sx + 1];

                float wx; int x;
                if (xi == 0)      { wx = tx0.x; x = __float_as_int(tx0.z); }
                else if (xi == 1) { wx = tx0.y; x = __float_as_int(tx0.w); }
                else if (xi == 2) { wx = tx1.x; x = __float_as_int(tx1.z); }
                else              { wx = tx1.y; x = __float_as_int(tx1.w); }

                int y0 = __float_as_int(ty0.z) * W;
                int y1 = __float_as_int(ty0.w) * W;
                int y2 = __float_as_int(ty1.z) * W;
                int y3 = __float_as_int(ty1.w) * W;

                // All 4 phases' gathers issued as one batch (16 indep. LDGs).
                const float* fp0 = fl[l] + (size_t)(cq      ) * (W * W);
                const float* fp1 = fl[l] + (size_t)(cq +  64) * (W * W);
                const float* fp2 = fl[l] + (size_t)(cq + 128) * (W * W);
                const float* fp3 = fl[l] + (size_t)(cq + 192) * (W * W);

                float a0 = fp0[y0+x], b0 = fp0[y1+x], c0 = fp0[y2+x], d0 = fp0[y3+x];
                float a1 = fp1[y0+x], b1 = fp1[y1+x], c1 = fp1[y2+x], d1 = fp1[y3+x];
                float a2 = fp2[y0+x], b2 = fp2[y1+x], c2 = fp2[y2+x], d2 = fp2[y3+x];
                float a3 = fp3[y0+x], b3 = fp3[y1+x], c3 = fp3[y2+x], d3 = fp3[y3+x];

                float s0 = wx * (ty0.x*a0 + ty0.y*b0 + ty1.x*c0 + ty1.y*d0);
                float s1 = wx * (ty0.x*a1 + ty0.y*b1 + ty1.x*c1 + ty1.y*d1);
                float s2 = wx * (ty0.x*a2 + ty0.y*b2 + ty1.x*c2 + ty1.y*d2);
                float s3 = wx * (ty0.x*a3 + ty0.y*b3 + ty1.x*c3 + ty1.y*d3);

                s0 += __shfl_xor_sync(0xFFFFFFFFu, s0, 1);
                s1 += __shfl_xor_sync(0xFFFFFFFFu, s1, 1);
                s2 += __shfl_xor_sync(0xFFFFFFFFu, s2, 1);
                s3 += __shfl_xor_sync(0xFFFFFFFFu, s3, 1);
                s0 += __shfl_xor_sync(0xFFFFFFFFu, s0, 2);
                s1 += __shfl_xor_sync(0xFFFFFFFFu, s1, 2);
                s2 += __shfl_xor_sync(0xFFFFFFFFu, s2, 2);
                s3 += __shfl_xor_sync(0xFFFFFFFFu, s3, 2);

                best0 = fmaxf(best0, s0 * 0.25f);
                best1 = fmaxf(best1, s1 * 0.25f);
                best2 = fmaxf(best2, s2 * 0.25f);
                best3 = fmaxf(best3, s3 * 0.25f);
            }
        }
        if (xi == 0) {
            out[obase + (size_t)(cq      ) * CELLS] = best0;
            out[obase + (size_t)(cq +  64) * CELLS] = best1;
            out[obase + (size_t)(cq + 128) * CELLS] = best2;
            out[obase + (size_t)(cq + 192) * CELLS] = best3;
        }
    }
}

__global__ __launch_bounds__(256, 4)
void afp_fused(const float* __restrict__ f0, const float* __restrict__ f1,
               const float* __restrict__ f2, const float* __restrict__ f3,
               const float* __restrict__ rois, int R, float* __restrict__ out)
{
    __shared__ ConsumeSmem cs;
    const int tid = threadIdx.x;
    const int bid = blockIdx.x;

    if (bid < R) {
        // ============================ BUILDER ============================
        __shared__ float s_w0[4][2][GSAMP];
        __shared__ float s_w1[4][2][GSAMP];
        __shared__ unsigned char s_m[CELLS];
        __shared__ unsigned char s_anyv[NGRP];

        const int r = bid;

        // Phase A: bilinear prep (reference fp32 op order, exactly).
        if (tid < 4 * 2 * GSAMP) {
            int l   = tid / (2 * GSAMP);
            int rem = tid - l * (2 * GSAMP);
            int a   = rem / GSAMP;       // 0=y, 1=x
            int j   = rem - a * GSAMP;

            float p1 = rois[r * 4 + (a == 0 ? 1 : 0)];
            float p2 = rois[r * 4 + (a == 0 ? 3 : 2)];
            #pragma unroll
            for (int i = 3; i >= 0; --i) {
                if (i >= l) {
                    float s = (float)(28 << i);
                    p1 = __fmul_rn(p1, s);
                    p2 = __fmul_rn(p2, s);
                }
            }
            float len  = fmaxf(__fadd_rn(p2, -p1), 1.0f);
            float t    = __fdiv_rn(len, 14.0f);
            float step = ((float)j + 0.5f) * 0.5f;
            float c    = __fadd_rn(p1, __fmul_rn(step, t));

            int L = 224 >> l;
            bool valid = (c >= -1.0f) && (c <= (float)L);
            c = fminf(fmaxf(c, 0.0f), (float)(L - 1));
            float lo   = floorf(c);
            float frac = __fadd_rn(c, -lo);
            int loi = (int)lo;
            int hii = loi + 1;
            if (loi >= L - 1) { loi = L - 1; hii = L - 1; frac = 0.0f; }
            float v  = valid ? 1.0f : 0.0f;
            float w0 = (1.0f - frac) * v;
            float w1 = frac * v;
            s_w0[l][a][j] = w0;
            s_w1[l][a][j] = w1;
            g_tab[r][l][a][j] = make_float4(w0, w1, __int_as_float(loi), __int_as_float(hii));
        }
        __syncthreads();

        // Phase B: mask + publish worklist entries.
        if (tid < CELLS) {
            int py = tid / OUTSZ;
            int px = tid - py * OUTSZ;
            unsigned m = 0;
            #pragma unroll
            for (int l = 0; l < 4; ++l) {
                float wy = s_w0[l][0][2*py]   + s_w1[l][0][2*py]
                         + s_w0[l][0][2*py+1] + s_w1[l][0][2*py+1];
                float wx = s_w0[l][1][2*px]   + s_w1[l][1][2*px]
                         + s_w0[l][1][2*px+1] + s_w1[l][1][2*px+1];
                if (wy > 0.0f && wx > 0.0f) m |= (1u << l);
            }
            s_m[tid] = (unsigned char)m;
            if (m) {
                int pos = atomicAdd(&g_count, 1);
                strel_u32(&g_work[pos],
                          ((unsigned)r << 12) | ((unsigned)tid << 4) | m);
            }
        }
        __syncthreads();

        if (tid == 0) {
            __threadfence();
            atomicAdd(&g_bdone, 1);
        }

        if (tid < NGRP) {
            int k = tid * 4;
            s_anyv[tid] = (unsigned char)(s_m[k] | s_m[k+1] | s_m[k+2] | s_m[k+3]);
        }
        __syncthreads();

        // Skip-fill: zero all invalid cells of this ROI's slice.
        float* obase = out + (size_t)r * (CH * CELLS);
        float4* o4 = reinterpret_cast<float4*>(obase);
        const float4 z4 = make_float4(0.f, 0.f, 0.f, 0.f);
        int k = tid % NGRP;
        #pragma unroll 4
        for (int i = tid; i < NF4; i += 256) {
            if (!s_anyv[k]) {
                o4[i] = z4;
            } else {
                int cell0 = k * 4;
                float* p = obase + i * 4;
                #pragma unroll
                for (int q = 0; q < 4; ++q)
                    if (!s_m[cell0 + q]) p[q] = 0.0f;
            }
            k += 256 % NGRP;             // 11
            if (k >= NGRP) k -= NGRP;
        }
        // Builders join the consumer pool after their fill.
        consume(f0, f1, f2, f3, out, R, &cs);
    } else {
        // ============================ CONSUMER ===========================
        consume(f0, f1, f2, f3, out, R, &cs);
    }

    // Self-reset: last block zeroes all counters for the next replay.
    __syncthreads();
    if (tid == 0) {
        int t = atomicAdd(&g_ticket, 1);
        if (t == R + CGRID - 1) {
            g_count  = 0;
            g_bdone  = 0;
            g_pop    = 0;
            g_ticket = 0;
        }
    }
}

extern "C" void kernel_launch(void* const* d_in, const int* in_sizes, int n_in,
                              void* d_out, int out_size)
{
    const float* f0   = (const float*)d_in[0];
    const float* f1   = (const float*)d_in[1];
    const float* f2   = (const float*)d_in[2];
    const float* f3   = (const float*)d_in[3];
    const float* rois = (const float*)d_in[4];
    int R = in_sizes[4] / 4;

    afp_fused<<<R + CGRID, 256>>>(f0, f1, f2, f3, rois, R, (float*)d_out);
}